// round 9
// baseline (speedup 1.0000x reference)
#include <cuda_runtime.h>
#include <math.h>

#define B_ 64
#define F_ 256
#define T_ 1024
#define H_ 1024
#define O_ 512

#define NB   128          // persistent blocks
#define BT   16           // b rows per block
#define HT2  32           // h cols per block (stored as 16 interleaved pairs)
#define KC   256          // k chunk staged in smem
#define NCH  (H_ / KC)    // 4 chunks

#define WROW2 (2 * H_ + 4)        // 2052 floats: interleaved (h, h+16) pairs
#define SROW2 (KC + 2)            // 258 float2 per sS2 row
// smem: Wh 16*2052*4 = 131,328 B ; sS2 2*16*258*8 = 66,048 B ; total 197,376 B
#define SMEM_RNN (16 * WROW2 * 4 + 2 * BT * SROW2 * 8)

// Scratch: buf[t][b][h]. xb before step t, state s_t after (in place).
__device__ float g_buf[(size_t)T_ * B_ * H_];   // 256 MB
__device__ unsigned g_flags[NB];                // barrier arrival flags
__device__ unsigned g_rel2;                     // barrier release (monotonic)

// ---------------------------------------------------------------------------
// PROVEN R3 barrier: distributed arrival flags, leader (block 0) scans with
// 128 threads, single release word polled by members. Monotonic epochs.
// ---------------------------------------------------------------------------
__device__ __forceinline__ void gsync(unsigned target) {
    __syncthreads();
    if (blockIdx.x == 0) {
        if (threadIdx.x == 0) {
            __threadfence();
            *(volatile unsigned*)&g_flags[0] = target;
        }
        unsigned i = threadIdx.x;       // 128 threads scan 128 flags
        while ((int)(*(volatile unsigned*)&g_flags[i] - target) < 0)
            __nanosleep(40);
        __syncthreads();
        if (threadIdx.x == 0) {
            __threadfence();
            *(volatile unsigned*)&g_rel2 = target;
        }
        __syncthreads();
    } else {
        if (threadIdx.x == 0) {
            __threadfence();            // order data before flag
            *(volatile unsigned*)&g_flags[blockIdx.x] = target;
            while ((int)(*(volatile unsigned*)&g_rel2 - target) < 0)
                __nanosleep(40);
            __threadfence();            // acquire + L1D refresh
        }
        __syncthreads();
    }
}

// ---- packed f32x2 helpers (sm_103a FFMA2 path; ptxas won't auto-fuse) ----
__device__ __forceinline__ void fma2(unsigned long long& a,
                                     unsigned long long x,
                                     unsigned long long y) {
    asm("fma.rn.f32x2 %0, %1, %2, %0;" : "+l"(a) : "l"(x), "l"(y));
}
__device__ __forceinline__ float2 unpk(unsigned long long v) {
    float2 f;
    asm("mov.b64 {%0, %1}, %2;" : "=f"(f.x), "=f"(f.y) : "l"(v));
    return f;
}

// ---------------------------------------------------------------------------
// Kernel 1: buf[t][b][h] = bias[h] + sum_f x[b][f][t] * Wx[f][h]
// Ping-pong smem, one __syncthreads per k-iter (measured 949-953us).
// ---------------------------------------------------------------------------
__global__ __launch_bounds__(256) void k_xw(const float* __restrict__ x,
                                            const float* __restrict__ Wx,
                                            const float* __restrict__ bias) {
    const int BM = 128, BN = 128, BK = 8, NC = F_ / BK;
    __shared__ float As[2][BK][BM];
    __shared__ float Bs[2][BK][BN];

    int tid = threadIdx.x;
    int tx = tid % 16, ty = tid / 16;
    int n0 = blockIdx.x * BN;
    int mtile = blockIdx.y;
    int b  = mtile / (T_ / BM);
    int t0 = (mtile % (T_ / BM)) * BM;

    const float* xb = x + (size_t)b * F_ * T_ + t0;

    const int lk = tid >> 5;
    const int lq = (tid & 31) * 4;

    float4 ra = *reinterpret_cast<const float4*>(&xb[(size_t)lk * T_ + lq]);
    float4 rb = *reinterpret_cast<const float4*>(&Wx[(size_t)lk * H_ + n0 + lq]);
    *reinterpret_cast<float4*>(&As[0][lk][lq]) = ra;
    *reinterpret_cast<float4*>(&Bs[0][lk][lq]) = rb;
    __syncthreads();

    float acc[8][8];
#pragma unroll
    for (int i = 0; i < 8; i++)
#pragma unroll
        for (int j = 0; j < 8; j++) acc[i][j] = 0.f;

    for (int c = 0; c < NC; ++c) {
        int cur = c & 1;
        if (c + 1 < NC) {
            ra = *reinterpret_cast<const float4*>(
                &xb[(size_t)((c + 1) * BK + lk) * T_ + lq]);
            rb = *reinterpret_cast<const float4*>(
                &Wx[(size_t)((c + 1) * BK + lk) * H_ + n0 + lq]);
        }
#pragma unroll
        for (int k = 0; k < BK; k++) {
            float va[8], vb[8];
#pragma unroll
            for (int i = 0; i < 8; i++) va[i] = As[cur][k][ty + 16 * i];
#pragma unroll
            for (int j = 0; j < 8; j++) vb[j] = Bs[cur][k][tx + 16 * j];
#pragma unroll
            for (int i = 0; i < 8; i++)
#pragma unroll
                for (int j = 0; j < 8; j++) acc[i][j] += va[i] * vb[j];
        }
        if (c + 1 < NC) {
            *reinterpret_cast<float4*>(&As[1 - cur][lk][lq]) = ra;
            *reinterpret_cast<float4*>(&Bs[1 - cur][lk][lq]) = rb;
            __syncthreads();
        }
    }

#pragma unroll
    for (int i = 0; i < 8; i++) {
        int t = t0 + ty + 16 * i;
        float* dst = g_buf + ((size_t)t * B_ + b) * H_ + n0;
#pragma unroll
        for (int j = 0; j < 8; j++) {
            int n = tx + 16 * j;
            dst[n] = acc[i][j] + bias[n0 + n];
        }
    }
}

// ---------------------------------------------------------------------------
// Kernel 2: persistent recurrence. Block bx: C[16 b][32 h], full K=1024.
// Wh resident in smem as interleaved (h, h+16) pairs; s staged PRE-DUPLICATED
// as (s,s) float2 so the hot loop is pure LDS.128 + fma.rn.f32x2 (no MOVs).
// 128 threads, 2b x 2h tile. KC=256 (4 chunks/step). R3 leader barrier.
// ---------------------------------------------------------------------------
__global__ __launch_bounds__(128, 1) void k_rnn(const float* __restrict__ Wh) {
    extern __shared__ float smem[];
    float*  sWh = smem;                          // [16][WROW2] pairs
    float2* sS2 = reinterpret_cast<float2*>(smem + 16 * WROW2);  // [2][BT][SROW2]

    const int tid = threadIdx.x;
    const int bx  = blockIdx.x;
    const int bt  = bx >> 5;                // 0..3
    const int ht  = bx & 31;                // 0..31
    const int b0  = bt * BT;
    const int h0  = ht * HT2;
    const int hIdx = tid & 15;              // h cols hIdx, hIdx+16
    const int bIdx = tid >> 4;              // b rows bIdx, bIdx+8

    // Load Wh slice once, pair-interleaved:
    // sWh[hh][2k+0] = Wh[k][h0+hh], sWh[hh][2k+1] = Wh[k][h0+hh+16]
    for (int i = tid; i < 16 * H_; i += 128) {
        int hh = i & 15;
        int k  = i >> 4;
        sWh[(size_t)hh * WROW2 + 2 * k]     = Wh[(size_t)k * H_ + h0 + hh];
        sWh[(size_t)hh * WROW2 + 2 * k + 1] = Wh[(size_t)k * H_ + h0 + hh + 16];
    }
    __syncthreads();

    const float* wRow = &sWh[(size_t)hIdx * WROW2];

    unsigned base = *(volatile unsigned*)&g_rel2;
    unsigned bar = 0;

    const int gb0 = b0 + bIdx, gb1 = b0 + bIdx + 8;
    const int gh0 = h0 + hIdx, gh1 = h0 + hIdx + 16;

    // prefetch xb for t = 0
    float xb00 = g_buf[(size_t)gb0 * H_ + gh0];
    float xb01 = g_buf[(size_t)gb0 * H_ + gh1];
    float xb10 = g_buf[(size_t)gb1 * H_ + gh0];
    float xb11 = g_buf[(size_t)gb1 * H_ + gh1];

    for (int t = 0; t < T_; ++t) {
        float* cur = g_buf + (size_t)t * B_ * H_;

        unsigned long long accA = 0ull, accB = 0ull;  // (a00,a01), (a10,a11)

        if (t > 0) {
            const float* sp = g_buf + (size_t)(t - 1) * B_ * H_ + (size_t)b0 * H_;

            // preload chunk 0 (16 rows x 256 k = 1024 float4 / 128 thr = 8 each)
            float4 pv[8];
#pragma unroll
            for (int it = 0; it < 8; it++) {
                int idx = it * 128 + tid;
                int row = idx >> 6, q = idx & 63;
                pv[it] = *reinterpret_cast<const float4*>(
                    &sp[(size_t)row * H_ + q * 4]);
            }

            for (int c = 0; c < NCH; ++c) {
                float2* sb = sS2 + (c & 1) * (BT * SROW2);
                __syncthreads();
                // stage chunk c, duplicating each value: (v, v)
#pragma unroll
                for (int it = 0; it < 8; it++) {
                    int idx = it * 128 + tid;
                    int row = idx >> 6, q = idx & 63;
                    float2* d = &sb[row * SROW2 + q * 4];
                    float4 v = pv[it];
                    *reinterpret_cast<float4*>(d) =
                        make_float4(v.x, v.x, v.y, v.y);
                    *reinterpret_cast<float4*>(d + 2) =
                        make_float4(v.z, v.z, v.w, v.w);
                }
                __syncthreads();
                if (c + 1 < NCH) {
                    const float* spn = sp + (c + 1) * KC;
#pragma unroll
                    for (int it = 0; it < 8; it++) {
                        int idx = it * 128 + tid;
                        int row = idx >> 6, q = idx & 63;
                        pv[it] = *reinterpret_cast<const float4*>(
                            &spn[(size_t)row * H_ + q * 4]);
                    }
                }
                const float2* s0r = &sb[bIdx * SROW2];
                const float2* s1r = &sb[(bIdx + 8) * SROW2];
                const float* wr  = wRow + c * (KC * 2);
#pragma unroll 8
                for (int q = 0; q < KC / 4; q++) {
                    // packed (s,s) pairs: 2 LDS.128 per b-row per 4k
                    ulonglong2 sa0 = *reinterpret_cast<const ulonglong2*>(&s0r[q * 4]);
                    ulonglong2 sa1 = *reinterpret_cast<const ulonglong2*>(&s0r[q * 4 + 2]);
                    ulonglong2 sb0 = *reinterpret_cast<const ulonglong2*>(&s1r[q * 4]);
                    ulonglong2 sb1 = *reinterpret_cast<const ulonglong2*>(&s1r[q * 4 + 2]);
                    ulonglong2 wa = *reinterpret_cast<const ulonglong2*>(&wr[q * 8]);
                    ulonglong2 wb = *reinterpret_cast<const ulonglong2*>(&wr[q * 8 + 4]);
                    fma2(accA, sa0.x, wa.x); fma2(accB, sb0.x, wa.x);
                    fma2(accA, sa0.y, wa.y); fma2(accB, sb0.y, wa.y);
                    fma2(accA, sa1.x, wb.x); fma2(accB, sb1.x, wb.x);
                    fma2(accA, sa1.y, wb.y); fma2(accB, sb1.y, wb.y);
                }
            }
        }

        // epilogue: s_t = tanh(xb + acc), in place
        float2 rA = unpk(accA);
        float2 rB = unpk(accB);
        cur[(size_t)gb0 * H_ + gh0] = tanhf(xb00 + rA.x);
        cur[(size_t)gb0 * H_ + gh1] = tanhf(xb01 + rA.y);
        cur[(size_t)gb1 * H_ + gh0] = tanhf(xb10 + rB.x);
        cur[(size_t)gb1 * H_ + gh1] = tanhf(xb11 + rB.y);

        // prefetch next step's xb BEFORE the barrier (overlaps barrier wait)
        {
            const float* nxt = g_buf + (size_t)((t + 1 < T_) ? t + 1 : t) * B_ * H_;
            xb00 = nxt[(size_t)gb0 * H_ + gh0];
            xb01 = nxt[(size_t)gb0 * H_ + gh1];
            xb10 = nxt[(size_t)gb1 * H_ + gh0];
            xb11 = nxt[(size_t)gb1 * H_ + gh1];
        }

        gsync(base + (++bar));
    }
}

// ---------------------------------------------------------------------------
// Kernel 3: out[b][t][o] = bout[o] + sum_h buf[t][b][h] * Wout[h][o]
// Ping-pong smem, one __syncthreads per k-iter.
// ---------------------------------------------------------------------------
__global__ __launch_bounds__(256) void k_out(const float* __restrict__ Wout,
                                             const float* __restrict__ bout,
                                             float* __restrict__ out) {
    const int BM = 128, BN = 128, BK = 8, NC = H_ / BK;
    __shared__ float As[2][BK][BM + 4];
    __shared__ float Bs[2][BK][BN];

    int tid = threadIdx.x;
    int tx = tid % 16, ty = tid / 16;
    int n0 = blockIdx.x * BN;
    int m0 = blockIdx.y * BM;

    const float* A = g_buf;  // [m][k], m = t*B + b, K = H_

    const int mm = tid >> 1;
    const int kq = (tid & 1) * 4;
    const int lk = tid >> 5;
    const int lq = (tid & 31) * 4;

    float4 ra = *reinterpret_cast<const float4*>(&A[(size_t)(m0 + mm) * H_ + kq]);
    float4 rb = *reinterpret_cast<const float4*>(&Wout[(size_t)lk * O_ + n0 + lq]);
    As[0][kq + 0][mm] = ra.x;
    As[0][kq + 1][mm] = ra.y;
    As[0][kq + 2][mm] = ra.z;
    As[0][kq + 3][mm] = ra.w;
    *reinterpret_cast<float4*>(&Bs[0][lk][lq]) = rb;
    __syncthreads();

    float acc[8][8];
#pragma unroll
    for (int i = 0; i < 8; i++)
#pragma unroll
        for (int j = 0; j < 8; j++) acc[i][j] = 0.f;

    for (int c = 0; c < NC; ++c) {
        int cur = c & 1;
        if (c + 1 < NC) {
            ra = *reinterpret_cast<const float4*>(
                &A[(size_t)(m0 + mm) * H_ + (c + 1) * BK + kq]);
            rb = *reinterpret_cast<const float4*>(
                &Wout[(size_t)((c + 1) * BK + lk) * O_ + n0 + lq]);
        }
#pragma unroll
        for (int k = 0; k < BK; k++) {
            float va[8], vb[8];
#pragma unroll
            for (int i = 0; i < 8; i++) va[i] = As[cur][k][ty + 16 * i];
#pragma unroll
            for (int j = 0; j < 8; j++) vb[j] = Bs[cur][k][tx + 16 * j];
#pragma unroll
            for (int i = 0; i < 8; i++)
#pragma unroll
                for (int j = 0; j < 8; j++) acc[i][j] += va[i] * vb[j];
        }
        if (c + 1 < NC) {
            As[1 - cur][kq + 0][mm] = ra.x;
            As[1 - cur][kq + 1][mm] = ra.y;
            As[1 - cur][kq + 2][mm] = ra.z;
            As[1 - cur][kq + 3][mm] = ra.w;
            *reinterpret_cast<float4*>(&Bs[1 - cur][lk][lq]) = rb;
            __syncthreads();
        }
    }

    // m = t*B + b  ->  out[(b*T + t)*O + n]
#pragma unroll
    for (int i = 0; i < 8; i++) {
        int m = m0 + ty + 16 * i;
        int t = m >> 6;          // / B_
        int b = m & 63;          // % B_
        float* dst = out + ((size_t)b * T_ + t) * O_ + n0;
#pragma unroll
        for (int j = 0; j < 8; j++) {
            int n = tx + 16 * j;
            dst[n] = acc[i][j] + bout[n0 + n];
        }
    }
}

extern "C" void kernel_launch(void* const* d_in, const int* in_sizes, int n_in,
                              void* d_out, int out_size) {
    const float* x    = (const float*)d_in[0];
    const float* Wx   = (const float*)d_in[1];
    const float* Wh   = (const float*)d_in[2];
    const float* bias = (const float*)d_in[3];
    const float* Wout = (const float*)d_in[4];
    const float* bout = (const float*)d_in[5];
    float* out = (float*)d_out;

    (void)in_sizes; (void)n_in; (void)out_size;

    cudaFuncSetAttribute(k_rnn, cudaFuncAttributeMaxDynamicSharedMemorySize,
                         SMEM_RNN);

    dim3 g1(H_ / 128, (B_ * T_) / 128);   // (8, 512)
    k_xw<<<g1, 256>>>(x, Wx, bias);

    k_rnn<<<NB, 128, SMEM_RNN>>>(Wh);     // single persistent launch

    dim3 g3(O_ / 128, (B_ * T_) / 128);   // (4, 512)
    k_out<<<g3, 256>>>(Wout, bout, out);
}